// round 3
// baseline (speedup 1.0000x reference)
#include <cuda_runtime.h>

// Problem constants (from reference setup_inputs)
#define BB 4
#define DD 64
#define HWC (512*512)
#define KK 32

// Tiling
#define DG 8                 // channels per block
#define CP 8192              // pixels per chunk
#define T 256                // threads per block
#define NCHUNK (HWC/CP)      // 32
#define GPT (CP/(4*T))       // float4 groups per thread = 8

// Global scratch (no allocations allowed)
__device__ float g_sum[BB*KK*DD];   // per (b,k,d) feature sums
__device__ float g_sq[BB*KK];       // per (b,k) sum of ||f||^2
__device__ float g_cnt[BB*KK];      // per (b,k) pixel counts

__global__ void zero_kernel() {
    int t = blockIdx.x * blockDim.x + threadIdx.x;
    int n = BB*KK*DD;
    for (int i = t; i < n; i += gridDim.x * blockDim.x) g_sum[i] = 0.f;
    if (t < BB*KK) { g_sq[t] = 0.f; g_cnt[t] = 0.f; }
}

// One block: 8 channels x 8192 pixels of one image.
// SMEM: s_sum[K][T] + s_sq[K][T], column = tid -> bank = lane, conflict-free,
// race-free (each thread RMWs only its own column).
__global__ __launch_bounds__(T) void accum_kernel(
    const float* __restrict__ feats, const int* __restrict__ labels)
{
    extern __shared__ float smem[];
    float* s_sum = smem;            // KK*T floats
    float* s_sq  = smem + KK*T;     // KK*T floats

    const int t     = threadIdx.x;
    const int chunk = blockIdx.x;
    const int dg    = blockIdx.y;
    const int b     = blockIdx.z;
    const int pixBase = chunk * CP;
    const int lane = t & 31;
    const int w    = t >> 5;

    // zero SMEM bins
    for (int i = t; i < 2*KK*T; i += T) smem[i] = 0.f;

    // load & byte-pack labels for this chunk (values < 32 fit in a byte)
    unsigned lb[GPT];
    const int4* lp4 = (const int4*)(labels + (size_t)b * HWC + pixBase);
#pragma unroll
    for (int g = 0; g < GPT; ++g) {
        int4 l = lp4[g*T + t];
        lb[g] = ((unsigned)l.x & 31u) | (((unsigned)l.y & 31u) << 8)
              | (((unsigned)l.z & 31u) << 16) | (((unsigned)l.w & 31u) << 24);
    }

    // per-pixel squared-norm accumulators (registers, across the 8 channels)
    float4 sq[GPT];
#pragma unroll
    for (int g = 0; g < GPT; ++g) sq[g] = make_float4(0.f, 0.f, 0.f, 0.f);

    __syncthreads();

    for (int dc = 0; dc < DG; ++dc) {
        const int d = dg*DG + dc;
        const float4* fp = (const float4*)(feats + ((size_t)(b*DD + d)) * HWC + pixBase);
#pragma unroll
        for (int g = 0; g < GPT; ++g) {
            float4 v = fp[g*T + t];
            unsigned l = lb[g];
            int b0 = l & 31, b1 = (l >> 8) & 31, b2 = (l >> 16) & 31, b3 = (l >> 24) & 31;
            s_sum[b0*T + t] += v.x;  sq[g].x = fmaf(v.x, v.x, sq[g].x);
            s_sum[b1*T + t] += v.y;  sq[g].y = fmaf(v.y, v.y, sq[g].y);
            s_sum[b2*T + t] += v.z;  sq[g].z = fmaf(v.z, v.z, sq[g].z);
            s_sum[b3*T + t] += v.w;  sq[g].w = fmaf(v.w, v.w, sq[g].w);
        }
        __syncthreads();
        // flush per-channel sums: warp w reduces bins 4w..4w+3 (and zeroes them)
#pragma unroll
        for (int bbn = 0; bbn < 4; ++bbn) {
            int bin = w*4 + bbn;
            float p = 0.f;
#pragma unroll
            for (int j = 0; j < T/32; ++j) {
                int idx = bin*T + j*32 + lane;
                p += s_sum[idx];
                s_sum[idx] = 0.f;
            }
#pragma unroll
            for (int off = 16; off; off >>= 1) p += __shfl_xor_sync(0xffffffffu, p, off);
            if (lane == 0) atomicAdd(&g_sum[(b*KK + bin)*DD + d], p);
        }
        __syncthreads();
    }

    // flush squared-norm register accumulators into SMEM bins (own column)
#pragma unroll
    for (int g = 0; g < GPT; ++g) {
        unsigned l = lb[g];
        s_sq[(l & 31)*T + t]         += sq[g].x;
        s_sq[((l >> 8) & 31)*T + t]  += sq[g].y;
        s_sq[((l >> 16) & 31)*T + t] += sq[g].z;
        s_sq[((l >> 24) & 31)*T + t] += sq[g].w;
    }
    // counts: only channel-group 0 counts pixels (s_sum is zeroed again here)
    if (dg == 0) {
#pragma unroll
        for (int g = 0; g < GPT; ++g) {
            unsigned l = lb[g];
            s_sum[(l & 31)*T + t]         += 1.f;
            s_sum[((l >> 8) & 31)*T + t]  += 1.f;
            s_sum[((l >> 16) & 31)*T + t] += 1.f;
            s_sum[((l >> 24) & 31)*T + t] += 1.f;
        }
    }
    __syncthreads();
#pragma unroll
    for (int bbn = 0; bbn < 4; ++bbn) {
        int bin = w*4 + bbn;
        float p = 0.f, c = 0.f;
#pragma unroll
        for (int j = 0; j < T/32; ++j) {
            int idx = bin*T + j*32 + lane;
            p += s_sq[idx];
            c += s_sum[idx];
        }
#pragma unroll
        for (int off = 16; off; off >>= 1) {
            p += __shfl_xor_sync(0xffffffffu, p, off);
            c += __shfl_xor_sync(0xffffffffu, c, off);
        }
        if (lane == 0) {
            atomicAdd(&g_sq[b*KK + bin], p);
            if (dg == 0) atomicAdd(&g_cnt[b*KK + bin], c);
        }
    }
}

__global__ void finalize_kernel(float* __restrict__ out) {
    __shared__ float s_mean[KK*65];   // padded, conflict-free column reads
    __shared__ float s_m2[KK];
    __shared__ float s_cnt[KK];
    __shared__ float s_acc[3];        // var, hinge, reg
    __shared__ float s_tot;
    const int t = threadIdx.x;
    if (t == 0) s_tot = 0.f;

    for (int b = 0; b < BB; ++b) {
        if (t < 3) s_acc[t] = 0.f;
        if (t < KK) s_cnt[t] = g_cnt[b*KK + t];
        __syncthreads();
        for (int i = t; i < KK*DD; i += blockDim.x) {
            int k = i >> 6, d = i & 63;
            s_mean[k*65 + d] = g_sum[(b*KK + k)*DD + d] / fmaxf(s_cnt[k], 1.f);
        }
        __syncthreads();
        if (t < KK) {
            float m2 = 0.f;
#pragma unroll
            for (int d = 0; d < DD; ++d) { float m = s_mean[t*65 + d]; m2 = fmaf(m, m, m2); }
            s_m2[t] = m2;
            float c = s_cnt[t];
            if (c > 0.f) {
                // sum ||f - mu||^2 = sumsq - cnt*||mu||^2 ; var_per = that / cnt
                atomicAdd(&s_acc[0], (g_sq[b*KK + t] - c*m2) / c);
                atomicAdd(&s_acc[2], sqrtf(m2));
            }
        }
        __syncthreads();
        for (int p = t; p < KK*KK; p += blockDim.x) {
            int i = p >> 5, j = p & 31;
            if (j > i && s_cnt[i] > 0.f && s_cnt[j] > 0.f) {
                float dsq = 0.f;
#pragma unroll
                for (int d = 0; d < DD; ++d) {
                    float df = s_mean[i*65 + d] - s_mean[j*65 + d];
                    dsq = fmaf(df, df, dsq);
                }
                float dist = sqrtf(dsq);
                if (dist < 3.0f) {            // 2 * delta_d, delta_d = 1.5
                    float h = 3.0f - dist;
                    atomicAdd(&s_acc[1], h*h);
                }
            }
        }
        __syncthreads();
        if (t == 0) {
            float ncl = 0.f;
            for (int k = 0; k < KK; ++k) ncl += (s_cnt[k] > 0.f) ? 1.f : 0.f;
            float dist_loss = s_acc[1] / fmaxf(ncl - 1.f, 1.f);
            s_tot += (s_acc[0] + dist_loss + 0.001f * s_acc[2]) / fmaxf(ncl, 1.f);
        }
        __syncthreads();
    }
    if (t == 0) out[0] = s_tot / (float)(BB + 1);
}

extern "C" void kernel_launch(void* const* d_in, const int* in_sizes, int n_in,
                              void* d_out, int out_size) {
    const float* feats  = (const float*)d_in[0];
    const int*   labels = (const int*)d_in[1];
    float*       out    = (float*)d_out;

    cudaFuncSetAttribute(accum_kernel, cudaFuncAttributeMaxDynamicSharedMemorySize,
                         2*KK*T*(int)sizeof(float));

    zero_kernel<<<32, 256>>>();
    dim3 grid(NCHUNK, DD/DG, BB);
    accum_kernel<<<grid, T, 2*KK*T*sizeof(float)>>>(feats, labels);
    finalize_kernel<<<1, 256>>>(out);
}

// round 4
// speedup vs baseline: 1.1328x; 1.1328x over previous
#include <cuda_runtime.h>

// Problem constants
#define BB 4
#define DDIM 64
#define HW (512*512)
#define KK 32

// Tiling: each block = 4 channels (one quad) x CP pixels of one image.
#define T 256
#define CP 16384
#define NCHUNK (HW/CP)     // 16
#define PPT (CP/T)         // 64 pixels per thread
#define UB 8               // pixels per load batch
#define NB (PPT/UB)        // 8 batches
#define QG (DDIM/4)        // 16 channel quads

// Global scratch (no allocations allowed)
__device__ float g_sum[BB*KK*DDIM];   // per (b,k,d) feature sums
__device__ float g_sq[BB*KK];         // per (b,k) sum of ||f||^2
__device__ float g_cnt[BB*KK];        // per (b,k) pixel counts

__global__ void zero_kernel() {
    int t = blockIdx.x * blockDim.x + threadIdx.x;
    int n = BB*KK*DDIM;
    for (int i = t; i < n; i += gridDim.x * blockDim.x) g_sum[i] = 0.f;
    if (t < BB*KK) { g_sq[t] = 0.f; g_cnt[t] = 0.f; }
}

// SMEM layout (dynamic, 196608 B):
//   s4   : KK*T float4  (131072 B)  per-bin per-thread 4-channel partial sums
//   s_sq : KK*T float   ( 32768 B)  per-bin per-thread ||f||^2 partials (this quad)
//   s_cnt: KK*T float   ( 32768 B)  per-bin per-thread counts (quad 0 only)
// Column = tid -> bank = lane: conflict-free, race-free (each thread owns its column).
__global__ __launch_bounds__(T) void accum_kernel(
    const float* __restrict__ feats, const int* __restrict__ labels)
{
    extern __shared__ float smem[];
    float4* s4    = (float4*)smem;          // KK*T float4
    float*  s_sq  = smem + KK*T*4;          // KK*T floats
    float*  s_cnt = s_sq + KK*T;            // KK*T floats

    const int t     = threadIdx.x;
    const int chunk = blockIdx.x;
    const int q     = blockIdx.y;           // channel quad
    const int b     = blockIdx.z;
    const bool do_cnt = (q == 0);
    const int lane = t & 31;
    const int w    = t >> 5;

    // zero SMEM bins
    for (int i = t; i < KK*T; i += T) s4[i] = make_float4(0.f, 0.f, 0.f, 0.f);
    for (int i = t; i < KK*T; i += T) s_sq[i] = 0.f;
    if (do_cnt) for (int i = t; i < KK*T; i += T) s_cnt[i] = 0.f;
    __syncthreads();

    const size_t base = (size_t)(b*DDIM + q*4) * HW + (size_t)chunk * CP;
    const float* f0 = feats + base;
    const float* f1 = f0 + HW;
    const float* f2 = f1 + HW;
    const float* f3 = f2 + HW;
    const int*   lp = labels + (size_t)b * HW + (size_t)chunk * CP;

    auto load_batch = [&](int bt, int* lab, float4* v) {
        const int p0 = bt*UB*T + t;
#pragma unroll
        for (int u = 0; u < UB; ++u) lab[u] = lp[p0 + u*T] & 31;
#pragma unroll
        for (int u = 0; u < UB; ++u) {
            int idx = p0 + u*T;
            v[u].x = f0[idx];
            v[u].y = f1[idx];
            v[u].z = f2[idx];
            v[u].w = f3[idx];
        }
    };

    auto process = [&](const int* lab, const float4* v) {
#pragma unroll
        for (int u = 0; u < UB; ++u) {
            const int col = lab[u]*T + t;
            // 4-element RMW chain (one chain step per pixel, not per scalar)
            float4 cur = s4[col];
            cur.x += v[u].x; cur.y += v[u].y;
            cur.z += v[u].z; cur.w += v[u].w;
            s4[col] = cur;
            // independent chain: squared-norm partial for this quad
            float ss = v[u].x * v[u].x;
            ss = fmaf(v[u].y, v[u].y, ss);
            ss = fmaf(v[u].z, v[u].z, ss);
            ss = fmaf(v[u].w, v[u].w, ss);
            s_sq[col] += ss;
            // third independent chain: counts (quad 0 only)
            if (do_cnt) s_cnt[col] += 1.f;
        }
    };

    int  labA[UB], labB[UB];
    float4 vA[UB], vB[UB];

    // double-buffered: loads of batch n+1 overlap RMW chains of batch n
    load_batch(0, labA, vA);
    for (int bt = 0; bt < NB; bt += 2) {
        if (bt + 1 < NB) load_batch(bt + 1, labB, vB);
        process(labA, vA);
        if (bt + 2 < NB) load_batch(bt + 2, labA, vA);
        if (bt + 1 < NB) process(labB, vB);
    }
    __syncthreads();

    // flush: warp w reduces bins 4w..4w+3 across the 256 columns
#pragma unroll
    for (int bbn = 0; bbn < 4; ++bbn) {
        const int bin = w*4 + bbn;
        float4 a = make_float4(0.f, 0.f, 0.f, 0.f);
        float sq = 0.f, cn = 0.f;
#pragma unroll
        for (int j = 0; j < T/32; ++j) {
            const int col = bin*T + j*32 + lane;
            float4 x = s4[col];
            a.x += x.x; a.y += x.y; a.z += x.z; a.w += x.w;
            sq += s_sq[col];
            if (do_cnt) cn += s_cnt[col];
        }
#pragma unroll
        for (int off = 16; off; off >>= 1) {
            a.x += __shfl_xor_sync(0xffffffffu, a.x, off);
            a.y += __shfl_xor_sync(0xffffffffu, a.y, off);
            a.z += __shfl_xor_sync(0xffffffffu, a.z, off);
            a.w += __shfl_xor_sync(0xffffffffu, a.w, off);
            sq  += __shfl_xor_sync(0xffffffffu, sq,  off);
            cn  += __shfl_xor_sync(0xffffffffu, cn,  off);
        }
        if (lane < 4) {
            float val = (lane == 0) ? a.x : (lane == 1) ? a.y : (lane == 2) ? a.z : a.w;
            atomicAdd(&g_sum[(b*KK + bin)*DDIM + q*4 + lane], val);
        }
        if (lane == 4)            atomicAdd(&g_sq[b*KK + bin], sq);
        if (do_cnt && lane == 5)  atomicAdd(&g_cnt[b*KK + bin], cn);
    }
}

__global__ void finalize_kernel(float* __restrict__ out) {
    __shared__ float s_mean[KK*65];   // padded, conflict-free column reads
    __shared__ float s_cnt[KK];
    __shared__ float s_acc[3];        // var, hinge, reg
    __shared__ float s_tot;
    const int t = threadIdx.x;
    if (t == 0) s_tot = 0.f;

    for (int b = 0; b < BB; ++b) {
        if (t < 3) s_acc[t] = 0.f;
        if (t < KK) s_cnt[t] = g_cnt[b*KK + t];
        __syncthreads();
        for (int i = t; i < KK*DDIM; i += blockDim.x) {
            int k = i >> 6, d = i & 63;
            s_mean[k*65 + d] = g_sum[(b*KK + k)*DDIM + d] / fmaxf(s_cnt[k], 1.f);
        }
        __syncthreads();
        if (t < KK) {
            float m2 = 0.f;
#pragma unroll
            for (int d = 0; d < DDIM; ++d) { float m = s_mean[t*65 + d]; m2 = fmaf(m, m, m2); }
            float c = s_cnt[t];
            if (c > 0.f) {
                // sum ||f - mu||^2 = sumsq - cnt*||mu||^2 ; var_per = that / cnt
                atomicAdd(&s_acc[0], (g_sq[b*KK + t] - c*m2) / c);
                atomicAdd(&s_acc[2], sqrtf(m2));
            }
        }
        __syncthreads();
        for (int p = t; p < KK*KK; p += blockDim.x) {
            int i = p >> 5, j = p & 31;
            if (j > i && s_cnt[i] > 0.f && s_cnt[j] > 0.f) {
                float dsq = 0.f;
#pragma unroll
                for (int d = 0; d < DDIM; ++d) {
                    float df = s_mean[i*65 + d] - s_mean[j*65 + d];
                    dsq = fmaf(df, df, dsq);
                }
                float dist = sqrtf(dsq);
                if (dist < 3.0f) {            // 2 * delta_d, delta_d = 1.5
                    float h = 3.0f - dist;
                    atomicAdd(&s_acc[1], h*h);
                }
            }
        }
        __syncthreads();
        if (t == 0) {
            float ncl = 0.f;
            for (int k = 0; k < KK; ++k) ncl += (s_cnt[k] > 0.f) ? 1.f : 0.f;
            float dist_loss = s_acc[1] / fmaxf(ncl - 1.f, 1.f);
            s_tot += (s_acc[0] + dist_loss + 0.001f * s_acc[2]) / fmaxf(ncl, 1.f);
        }
        __syncthreads();
    }
    if (t == 0) out[0] = s_tot / (float)(BB + 1);
}

extern "C" void kernel_launch(void* const* d_in, const int* in_sizes, int n_in,
                              void* d_out, int out_size) {
    const float* feats  = (const float*)d_in[0];
    const int*   labels = (const int*)d_in[1];
    float*       out    = (float*)d_out;

    const int smem_bytes = KK*T*6*(int)sizeof(float);   // 196608
    cudaFuncSetAttribute(accum_kernel, cudaFuncAttributeMaxDynamicSharedMemorySize,
                         smem_bytes);

    zero_kernel<<<32, 256>>>();
    dim3 grid(NCHUNK, QG, BB);
    accum_kernel<<<grid, T, smem_bytes>>>(feats, labels);
    finalize_kernel<<<1, 256>>>(out);
}